// round 8
// baseline (speedup 1.0000x reference)
#include <cuda_runtime.h>
#include <math.h>
#include <stdint.h>

// Problem-fixed sizes: N=100000, E=3200000, NF=16, H=32, HO=64
#define NMAX 100000
#define NF 16
#define H  32
#define HO 64

__device__ float  g_agg[NMAX * NF];   // scatter-sum accumulator (zeroed in k_pre)
__device__ float  g_h1 [NMAX * H];
__device__ float  g_h2 [NMAX * H];
__device__ double g_s1 [2 * H];       // sum[32], sumsq[32]
__device__ double g_s2 [2 * H];
__device__ int    g_is64;

__device__ __forceinline__ float gelu_exact(float v) {
    return 0.5f * v * (1.0f + erff(v * 0.70710678118654752f));
}

// ---------------------------------------------------------------------------
// K0: zero g_agg + stats accumulators; detect edge_index dtype
// ---------------------------------------------------------------------------
__global__ __launch_bounds__(256) void k_pre(const int* __restrict__ eidx32,
                                             int n4 /* N*NF/4 */) {
    int i = blockIdx.x * blockDim.x + threadIdx.x;
    if (i < n4) ((float4*)g_agg)[i] = make_float4(0.f, 0.f, 0.f, 0.f);
    if (blockIdx.x == 0) {
        if (threadIdx.x < 2 * H)       g_s1[threadIdx.x]         = 0.0;
        else if (threadIdx.x < 4 * H)  g_s2[threadIdx.x - 2 * H] = 0.0;
        if (threadIdx.x == 0) {
            int nz = 0;
            #pragma unroll
            for (int k = 0; k < 64; k++) nz |= eidx32[2 * k + 1];
            g_is64 = (nz == 0) ? 1 : 0;
        }
    }
}

// ---------------------------------------------------------------------------
// K1: edge kernel, single launch, 4 threads/edge, grid-stride with 2-way
// manual software pipelining (edges gt and gt+stride handled per iteration,
// loads batched for MLP=2). Weights+bias live in registers.
// ---------------------------------------------------------------------------
__global__ __launch_bounds__(256) void k_edge(const float* __restrict__ x,
                                              const void*  __restrict__ eidx,
                                              const float* __restrict__ ea,
                                              const float* __restrict__ We,
                                              const float* __restrict__ be,
                                              int E) {
    int t = blockIdx.x * blockDim.x + threadIdx.x;
    int c = t & 3;

    float w[8][4];
    #pragma unroll
    for (int k = 0; k < 8; k++) {
        float4 wv = __ldg((const float4*)(We + k * 16) + c);
        w[k][0] = wv.x; w[k][1] = wv.y; w[k][2] = wv.z; w[k][3] = wv.w;
    }
    float4 bv = __ldg(((const float4*)be) + c);
    int is64 = g_is64;

    int total  = E * 4;
    int stride = gridDim.x * blockDim.x;   // multiple of 4
    const int* p32 = (const int*)eidx;

    int gt = t;
    // ---- pipelined pairs ----
    for (; gt + stride < total; gt += 2 * stride) {
        int e0 = gt >> 2;
        int e1 = (gt + stride) >> 2;

        int src0, dst0, src1, dst1;
        if (is64) {
            src0 = ((const int2*)eidx)[e0].x;
            src1 = ((const int2*)eidx)[e1].x;
            dst0 = ((const int2*)eidx)[e0 + E].x;
            dst1 = ((const int2*)eidx)[e1 + E].x;
        } else {
            src0 = p32[e0]; src1 = p32[e1];
            dst0 = p32[e0 + E]; dst1 = p32[e1 + E];
        }

        const float4* ear0 = (const float4*)(ea + (size_t)e0 * 8);
        const float4* ear1 = (const float4*)(ea + (size_t)e1 * 8);
        float4 a00 = __ldg(ear0);
        float4 a01 = __ldg(ear0 + 1);
        float4 a10 = __ldg(ear1);
        float4 a11 = __ldg(ear1 + 1);

        // issue gathers early (independent of FMA chains)
        float4 xv0 = __ldg((const float4*)(x + (size_t)src0 * 16) + c);
        float4 xv1 = __ldg((const float4*)(x + (size_t)src1 * 16) + c);

        float av0[8] = {a00.x, a00.y, a00.z, a00.w, a01.x, a01.y, a01.z, a01.w};
        float av1[8] = {a10.x, a10.y, a10.z, a10.w, a11.x, a11.y, a11.z, a11.w};

        float m00 = bv.x, m01 = bv.y, m02 = bv.z, m03 = bv.w;
        float m10 = bv.x, m11 = bv.y, m12 = bv.z, m13 = bv.w;
        #pragma unroll
        for (int k = 0; k < 8; k++) {
            m00 = fmaf(av0[k], w[k][0], m00);
            m10 = fmaf(av1[k], w[k][0], m10);
            m01 = fmaf(av0[k], w[k][1], m01);
            m11 = fmaf(av1[k], w[k][1], m11);
            m02 = fmaf(av0[k], w[k][2], m02);
            m12 = fmaf(av1[k], w[k][2], m12);
            m03 = fmaf(av0[k], w[k][3], m03);
            m13 = fmaf(av1[k], w[k][3], m13);
        }

        float4 r0, r1;
        r0.x = fmaxf(xv0.x + m00, 0.0f);
        r0.y = fmaxf(xv0.y + m01, 0.0f);
        r0.z = fmaxf(xv0.z + m02, 0.0f);
        r0.w = fmaxf(xv0.w + m03, 0.0f);
        r1.x = fmaxf(xv1.x + m10, 0.0f);
        r1.y = fmaxf(xv1.y + m11, 0.0f);
        r1.z = fmaxf(xv1.z + m12, 0.0f);
        r1.w = fmaxf(xv1.w + m13, 0.0f);
        atomicAdd((float4*)(g_agg + (size_t)dst0 * 16) + c, r0);
        atomicAdd((float4*)(g_agg + (size_t)dst1 * 16) + c, r1);
    }
    // ---- remainder ----
    for (; gt < total; gt += stride) {
        int e = gt >> 2;
        int src, dst;
        if (is64) {
            src = ((const int2*)eidx)[e].x;
            dst = ((const int2*)eidx)[e + E].x;
        } else {
            src = p32[e]; dst = p32[e + E];
        }
        const float4* ear = (const float4*)(ea + (size_t)e * 8);
        float4 a0 = __ldg(ear);
        float4 a1 = __ldg(ear + 1);
        float4 xv = __ldg((const float4*)(x + (size_t)src * 16) + c);
        float av[8] = {a0.x, a0.y, a0.z, a0.w, a1.x, a1.y, a1.z, a1.w};
        float m0 = bv.x, m1 = bv.y, m2 = bv.z, m3 = bv.w;
        #pragma unroll
        for (int k = 0; k < 8; k++) {
            m0 = fmaf(av[k], w[k][0], m0);
            m1 = fmaf(av[k], w[k][1], m1);
            m2 = fmaf(av[k], w[k][2], m2);
            m3 = fmaf(av[k], w[k][3], m3);
        }
        float4 r;
        r.x = fmaxf(xv.x + m0, 0.0f);
        r.y = fmaxf(xv.y + m1, 0.0f);
        r.z = fmaxf(xv.z + m2, 0.0f);
        r.w = fmaxf(xv.w + m3, 0.0f);
        atomicAdd((float4*)(g_agg + (size_t)dst * 16) + c, r);
    }
}

// ---------------------------------------------------------------------------
// stats epilogue, two-pass half-size transpose:
// lanes 0..15 reduce sums, lanes 16..31 reduce sumsq of the same 16 features.
// ---------------------------------------------------------------------------
__device__ __forceinline__ void stats_epilogue(const float* acc, bool valid,
                                               double* sums) {
    __shared__ float tr[8][16][33];
    __shared__ float comb[8][32];
    int lane = threadIdx.x & 31;
    int wid  = threadIdx.x >> 5;
    int f    = lane & 15;
    bool isq = lane >= 16;

    float red[2];
    #pragma unroll
    for (int half = 0; half < 2; half++) {
        if (half) __syncwarp();
        #pragma unroll
        for (int j = 0; j < 16; j++)
            tr[wid][j][lane] = valid ? acc[half * 16 + j] : 0.0f;
        __syncwarp();
        float r = 0.0f;
        #pragma unroll
        for (int k = 0; k < 32; k++) {
            float v = tr[wid][f][k];
            r = fmaf(v, isq ? v : 1.0f, r);
        }
        red[half] = r;
    }

    #pragma unroll
    for (int half = 0; half < 2; half++) {
        comb[wid][lane] = red[half];
        __syncthreads();
        if (wid == 0) {
            float tsum = 0.0f;
            #pragma unroll
            for (int w = 0; w < 8; w++) tsum += comb[w][lane];
            atomicAdd(&sums[(isq ? 32 : 0) + half * 16 + f], (double)tsum);
        }
        __syncthreads();
    }
}

// ---------------------------------------------------------------------------
// BN finalize inline
// ---------------------------------------------------------------------------
__device__ __forceinline__ void fin_inline(const double* __restrict__ sums,
                                           const float* __restrict__ gamma,
                                           const float* __restrict__ beta,
                                           int N, float* ssc, float* ssh) {
    if (threadIdx.x < H) {
        int f = threadIdx.x;
        double mean = sums[f] / (double)N;
        double var  = sums[H + f] / (double)N - mean * mean;
        double inv  = 1.0 / sqrt(var + 1e-5);
        ssc[f] = (float)((double)gamma[f] * inv);
        ssh[f] = (float)((double)beta[f] - mean * (double)gamma[f] * inv);
    }
}

// ---------------------------------------------------------------------------
// K2: h1 = ((1+eps)*x + agg) @ W1 + b1   (+ fused BN1 stats) — streamed inputs
// ---------------------------------------------------------------------------
__global__ __launch_bounds__(256) void k_gemm1(const float* __restrict__ x,
                                               const float* __restrict__ epsp,
                                               const float* __restrict__ W1,
                                               const float* __restrict__ b1,
                                               int N) {
    __shared__ float sW[NF * H];
    __shared__ float sb[H];
    for (int i = threadIdx.x; i < NF * H; i += blockDim.x) sW[i] = W1[i];
    if (threadIdx.x < H) sb[threadIdx.x] = b1[threadIdx.x];
    __syncthreads();

    int n = blockIdx.x * blockDim.x + threadIdx.x;
    bool valid = n < N;
    float sc = 1.0f + epsp[0];
    int nc = valid ? n : 0;

    const float4* ar = (const float4*)(g_agg + (size_t)nc * NF);
    const float4* xr = (const float4*)(x     + (size_t)nc * NF);

    float acc[H];
    #pragma unroll
    for (int j = 0; j < H; j++) acc[j] = sb[j];

    #pragma unroll 1
    for (int cph = 0; cph < 4; cph++) {
        float4 v  = ar[cph];
        float4 xv = xr[cph];
        float a0 = fmaf(sc, xv.x, v.x);
        float a1 = fmaf(sc, xv.y, v.y);
        float a2 = fmaf(sc, xv.z, v.z);
        float a3 = fmaf(sc, xv.w, v.w);
        const float* w0 = sW + (4 * cph + 0) * H;
        const float* w1 = sW + (4 * cph + 1) * H;
        const float* w2 = sW + (4 * cph + 2) * H;
        const float* w3 = sW + (4 * cph + 3) * H;
        #pragma unroll
        for (int j = 0; j < H; j++) {
            float t0 = fmaf(a0, w0[j], acc[j]);
            float t1 = fmaf(a1, w1[j], t0);
            float t2 = fmaf(a2, w2[j], t1);
            acc[j]   = fmaf(a3, w3[j], t2);
        }
    }

    if (valid) {
        float4* hr = (float4*)(g_h1 + (size_t)n * H);
        #pragma unroll
        for (int cph = 0; cph < H / 4; cph++)
            hr[cph] = make_float4(acc[4*cph], acc[4*cph+1], acc[4*cph+2], acc[4*cph+3]);
    }
    stats_epilogue(acc, valid, g_s1);
}

// ---------------------------------------------------------------------------
// K3: h2 = gelu(bn1(h1)) @ W2 + b2   (streamed; BN1 inline; fused BN2 stats)
// ---------------------------------------------------------------------------
__global__ __launch_bounds__(256) void k_gemm2(const float* __restrict__ g1,
                                               const float* __restrict__ bt1,
                                               const float* __restrict__ W2,
                                               const float* __restrict__ b2,
                                               int N) {
    __shared__ float sW[H * H];
    __shared__ float sb[H], ssc[H], ssh[H];
    for (int i = threadIdx.x; i < H * H; i += blockDim.x) sW[i] = W2[i];
    if (threadIdx.x < H) sb[threadIdx.x] = b2[threadIdx.x];
    fin_inline(g_s1, g1, bt1, N, ssc, ssh);
    __syncthreads();

    int n = blockIdx.x * blockDim.x + threadIdx.x;
    bool valid = n < N;
    int nc = valid ? n : 0;
    const float4* hr = (const float4*)(g_h1 + (size_t)nc * H);

    float acc[H];
    #pragma unroll
    for (int j = 0; j < H; j++) acc[j] = sb[j];

    #pragma unroll 1
    for (int cph = 0; cph < 8; cph++) {
        float4 v = hr[cph];
        float y0 = gelu_exact(fmaf(v.x, ssc[4*cph+0], ssh[4*cph+0]));
        float y1 = gelu_exact(fmaf(v.y, ssc[4*cph+1], ssh[4*cph+1]));
        float y2 = gelu_exact(fmaf(v.z, ssc[4*cph+2], ssh[4*cph+2]));
        float y3 = gelu_exact(fmaf(v.w, ssc[4*cph+3], ssh[4*cph+3]));
        const float* w0 = sW + (4 * cph + 0) * H;
        const float* w1 = sW + (4 * cph + 1) * H;
        const float* w2 = sW + (4 * cph + 2) * H;
        const float* w3 = sW + (4 * cph + 3) * H;
        #pragma unroll
        for (int j = 0; j < H; j++) {
            float t0 = fmaf(y0, w0[j], acc[j]);
            float t1 = fmaf(y1, w1[j], t0);
            float t2 = fmaf(y2, w2[j], t1);
            acc[j]   = fmaf(y3, w3[j], t2);
        }
    }

    if (valid) {
        float4* o = (float4*)(g_h2 + (size_t)n * H);
        #pragma unroll
        for (int cph = 0; cph < H / 4; cph++)
            o[cph] = make_float4(acc[4*cph], acc[4*cph+1], acc[4*cph+2], acc[4*cph+3]);
    }
    stats_epilogue(acc, valid, g_s2);
}

// ---------------------------------------------------------------------------
// K4: out = gelu(bn2(h2)) @ W3 + b3   (streamed; two 32-output passes)
// ---------------------------------------------------------------------------
__global__ __launch_bounds__(256) void k_out(const float* __restrict__ g2,
                                             const float* __restrict__ bt2,
                                             const float* __restrict__ W3,
                                             const float* __restrict__ b3,
                                             float* __restrict__ out,
                                             int N) {
    __shared__ float sW[H * HO];
    __shared__ float sb[HO], ssc[H], ssh[H];
    for (int i = threadIdx.x; i < H * HO; i += blockDim.x) sW[i] = W3[i];
    if (threadIdx.x < HO) sb[threadIdx.x] = b3[threadIdx.x];
    fin_inline(g_s2, g2, bt2, N, ssc, ssh);
    __syncthreads();

    int n = blockIdx.x * blockDim.x + threadIdx.x;
    if (n >= N) return;
    const float4* hr = (const float4*)(g_h2 + (size_t)n * H);
    float4* orow = (float4*)(out + (size_t)n * HO);

    #pragma unroll 1
    for (int jb = 0; jb < 2; jb++) {
        float acc[32];
        #pragma unroll
        for (int j = 0; j < 32; j++) acc[j] = sb[jb * 32 + j];

        #pragma unroll 1
        for (int cph = 0; cph < 8; cph++) {
            float4 v = hr[cph];
            float y0 = gelu_exact(fmaf(v.x, ssc[4*cph+0], ssh[4*cph+0]));
            float y1 = gelu_exact(fmaf(v.y, ssc[4*cph+1], ssh[4*cph+1]));
            float y2 = gelu_exact(fmaf(v.z, ssc[4*cph+2], ssh[4*cph+2]));
            float y3 = gelu_exact(fmaf(v.w, ssc[4*cph+3], ssh[4*cph+3]));
            const float* w0 = sW + (4 * cph + 0) * HO + jb * 32;
            const float* w1 = sW + (4 * cph + 1) * HO + jb * 32;
            const float* w2 = sW + (4 * cph + 2) * HO + jb * 32;
            const float* w3 = sW + (4 * cph + 3) * HO + jb * 32;
            #pragma unroll
            for (int j = 0; j < 32; j++) {
                float t0 = fmaf(y0, w0[j], acc[j]);
                float t1 = fmaf(y1, w1[j], t0);
                float t2 = fmaf(y2, w2[j], t1);
                acc[j]   = fmaf(y3, w3[j], t2);
            }
        }
        #pragma unroll
        for (int cph = 0; cph < 8; cph++)
            orow[jb * 8 + cph] = make_float4(acc[4*cph], acc[4*cph+1],
                                             acc[4*cph+2], acc[4*cph+3]);
    }
}

// ---------------------------------------------------------------------------
extern "C" void kernel_launch(void* const* d_in, const int* in_sizes, int n_in,
                              void* d_out, int out_size) {
    const float* x    = (const float*)d_in[0];
    const void*  eidx =               d_in[1];
    const float* ea   = (const float*)d_in[2];
    const float* We   = (const float*)d_in[3];
    const float* be   = (const float*)d_in[4];
    const float* W1   = (const float*)d_in[5];
    const float* b1   = (const float*)d_in[6];
    const float* g1   = (const float*)d_in[7];
    const float* bt1  = (const float*)d_in[8];
    const float* W2   = (const float*)d_in[9];
    const float* b2   = (const float*)d_in[10];
    const float* epsp = (const float*)d_in[11];
    const float* g2   = (const float*)d_in[12];
    const float* bt2  = (const float*)d_in[13];
    const float* W3   = (const float*)d_in[14];
    const float* b3   = (const float*)d_in[15];
    float* out = (float*)d_out;

    int N = in_sizes[0] / NF;
    int E = in_sizes[2] / 8;
    int n4 = N * NF / 4;
    int nb = (N + 255) / 256;

    k_pre  <<<(n4 + 255) / 256, 256>>>((const int*)eidx, n4);
    k_edge <<<2048, 256>>>(x, eidx, ea, We, be, E);   // single launch, pipelined
    k_gemm1<<<nb, 256>>>(x, epsp, W1, b1, N);
    k_gemm2<<<nb, 256>>>(g1, bt1, W2, b2, N);         // profiled (idx 3)
    k_out  <<<nb, 256>>>(g2, bt2, W3, b3, out, N);
}

// round 9
// speedup vs baseline: 1.0684x; 1.0684x over previous
#include <cuda_runtime.h>
#include <math.h>
#include <stdint.h>

// Problem-fixed sizes: N=100000, E=3200000, NF=16, H=32, HO=64
#define NMAX 100000
#define NF 16
#define H  32
#define HO 64
#define NBANK 8

__device__ float  g_agg[NMAX * NF];
__device__ float  g_h1 [NMAX * H];
__device__ float  g_h2 [NMAX * H];
__device__ double g_s1 [NBANK * 64];   // per-bank: sum[32], sumsq[32]
__device__ double g_s2 [NBANK * 64];
__device__ int    g_is64;

__device__ __forceinline__ float gelu_exact(float v) {
    return 0.5f * v * (1.0f + erff(v * 0.70710678118654752f));
}

// ---------------------------------------------------------------------------
// K0a: zero g_agg
// ---------------------------------------------------------------------------
__global__ __launch_bounds__(256) void k_pre_a(int n4) {
    int i = blockIdx.x * blockDim.x + threadIdx.x;
    if (i < n4) ((float4*)g_agg)[i] = make_float4(0.f, 0.f, 0.f, 0.f);
}
// K0b: zero banked stats
__global__ void k_pre_b() {
    int i = threadIdx.x;
    #pragma unroll
    for (int k = 0; k < NBANK * 64 / 256; k++) {
        g_s1[i + k * 256] = 0.0;
        g_s2[i + k * 256] = 0.0;
    }
}
// K0c: detect edge_index dtype
__global__ void k_pre_c(const int* __restrict__ eidx32) {
    if (threadIdx.x == 0) {
        int nz = 0;
        #pragma unroll
        for (int k = 0; k < 64; k++) nz |= eidx32[2 * k + 1];
        g_is64 = (nz == 0) ? 1 : 0;
    }
}

// ---------------------------------------------------------------------------
// K1: edge kernel. 4 threads/edge, grid-stride, simple body + index prefetch.
// Streaming data (indices, edge_attr) uses __ldcs so x/agg stay cache-hot.
// ---------------------------------------------------------------------------
__global__ __launch_bounds__(256) void k_edge(const float* __restrict__ x,
                                              const void*  __restrict__ eidx,
                                              const float* __restrict__ ea,
                                              const float* __restrict__ We,
                                              const float* __restrict__ be,
                                              int E) {
    int t = blockIdx.x * blockDim.x + threadIdx.x;
    int c = t & 3;

    float w[8][4];
    #pragma unroll
    for (int k = 0; k < 8; k++) {
        float4 wv = __ldg((const float4*)(We + k * 16) + c);
        w[k][0] = wv.x; w[k][1] = wv.y; w[k][2] = wv.z; w[k][3] = wv.w;
    }
    float4 bv = __ldg(((const float4*)be) + c);
    int is64 = g_is64;

    int total  = E * 4;
    int stride = gridDim.x * blockDim.x;   // multiple of 4
    const int*       p32 = (const int*)eidx;
    const long long* p64 = (const long long*)eidx;

    int gt = t;
    if (gt >= total) return;

    // prefetch first indices
    int src, dst;
    {
        int e = gt >> 2;
        if (is64) { src = (int)__ldcs(p64 + e); dst = (int)__ldcs(p64 + e + E); }
        else      { src = __ldcs(p32 + e);      dst = __ldcs(p32 + e + E);      }
    }

    while (gt < total) {
        int gtn = gt + stride;
        int srcN = 0, dstN = 0;
        if (gtn < total) {
            int en = gtn >> 2;
            if (is64) { srcN = (int)__ldcs(p64 + en); dstN = (int)__ldcs(p64 + en + E); }
            else      { srcN = __ldcs(p32 + en);      dstN = __ldcs(p32 + en + E);      }
        }

        int e = gt >> 2;
        // gather first (src already known from prefetch)
        float4 xv = __ldg((const float4*)(x + (size_t)src * 16) + c);
        const float4* ear = (const float4*)(ea + (size_t)e * 8);
        float4 a0 = __ldcs(ear);
        float4 a1 = __ldcs(ear + 1);
        float av[8] = {a0.x, a0.y, a0.z, a0.w, a1.x, a1.y, a1.z, a1.w};

        float m0 = bv.x, m1 = bv.y, m2 = bv.z, m3 = bv.w;
        #pragma unroll
        for (int k = 0; k < 8; k++) {
            m0 = fmaf(av[k], w[k][0], m0);
            m1 = fmaf(av[k], w[k][1], m1);
            m2 = fmaf(av[k], w[k][2], m2);
            m3 = fmaf(av[k], w[k][3], m3);
        }

        float4 r;
        r.x = fmaxf(xv.x + m0, 0.0f);
        r.y = fmaxf(xv.y + m1, 0.0f);
        r.z = fmaxf(xv.z + m2, 0.0f);
        r.w = fmaxf(xv.w + m3, 0.0f);
        atomicAdd((float4*)(g_agg + (size_t)dst * 16) + c, r);

        gt = gtn; src = srcN; dst = dstN;
    }
}

// ---------------------------------------------------------------------------
// stats epilogue: half-transpose reduction, banked double atomics
// ---------------------------------------------------------------------------
__device__ __forceinline__ void stats_epilogue(const float* acc, bool valid,
                                               double* sums) {
    __shared__ float tr[8][16][33];
    __shared__ float comb[8][32];
    int lane = threadIdx.x & 31;
    int wid  = threadIdx.x >> 5;
    int f    = lane & 15;
    bool isq = lane >= 16;
    int bank = blockIdx.x & (NBANK - 1);

    float red[2];
    #pragma unroll
    for (int half = 0; half < 2; half++) {
        if (half) __syncwarp();
        #pragma unroll
        for (int j = 0; j < 16; j++)
            tr[wid][j][lane] = valid ? acc[half * 16 + j] : 0.0f;
        __syncwarp();
        float r = 0.0f;
        #pragma unroll
        for (int k = 0; k < 32; k++) {
            float v = tr[wid][f][k];
            r = fmaf(v, isq ? v : 1.0f, r);
        }
        red[half] = r;
    }

    #pragma unroll
    for (int half = 0; half < 2; half++) {
        comb[wid][lane] = red[half];
        __syncthreads();
        if (wid == 0) {
            float tsum = 0.0f;
            #pragma unroll
            for (int w = 0; w < 8; w++) tsum += comb[w][lane];
            atomicAdd(&sums[bank * 64 + (isq ? 32 : 0) + half * 16 + f],
                      (double)tsum);
        }
        __syncthreads();
    }
}

// ---------------------------------------------------------------------------
// BN finalize inline: sum the 8 banks, then scale/shift
// ---------------------------------------------------------------------------
__device__ __forceinline__ void fin_inline(const double* __restrict__ sums,
                                           const float* __restrict__ gamma,
                                           const float* __restrict__ beta,
                                           int N, float* ssc, float* ssh) {
    if (threadIdx.x < H) {
        int f = threadIdx.x;
        double s = 0.0, q = 0.0;
        #pragma unroll
        for (int b = 0; b < NBANK; b++) {
            s += sums[b * 64 + f];
            q += sums[b * 64 + 32 + f];
        }
        double mean = s / (double)N;
        double var  = q / (double)N - mean * mean;
        double inv  = 1.0 / sqrt(var + 1e-5);
        ssc[f] = (float)((double)gamma[f] * inv);
        ssh[f] = (float)((double)beta[f] - mean * (double)gamma[f] * inv);
    }
}

// ---------------------------------------------------------------------------
// K2: h1 = ((1+eps)*x + agg) @ W1 + b1   (+ fused BN1 stats, streamed)
// ---------------------------------------------------------------------------
__global__ __launch_bounds__(256) void k_gemm1(const float* __restrict__ x,
                                               const float* __restrict__ epsp,
                                               const float* __restrict__ W1,
                                               const float* __restrict__ b1,
                                               int N) {
    __shared__ float sW[NF * H];
    __shared__ float sb[H];
    for (int i = threadIdx.x; i < NF * H; i += blockDim.x) sW[i] = W1[i];
    if (threadIdx.x < H) sb[threadIdx.x] = b1[threadIdx.x];
    __syncthreads();

    int n = blockIdx.x * blockDim.x + threadIdx.x;
    bool valid = n < N;
    float sc = 1.0f + epsp[0];
    int nc = valid ? n : 0;

    const float4* ar = (const float4*)(g_agg + (size_t)nc * NF);
    const float4* xr = (const float4*)(x     + (size_t)nc * NF);

    float acc[H];
    #pragma unroll
    for (int j = 0; j < H; j++) acc[j] = sb[j];

    #pragma unroll 1
    for (int cph = 0; cph < 4; cph++) {
        float4 v  = ar[cph];
        float4 xv = xr[cph];
        float a0 = fmaf(sc, xv.x, v.x);
        float a1 = fmaf(sc, xv.y, v.y);
        float a2 = fmaf(sc, xv.z, v.z);
        float a3 = fmaf(sc, xv.w, v.w);
        const float* w0 = sW + (4 * cph + 0) * H;
        const float* w1 = sW + (4 * cph + 1) * H;
        const float* w2 = sW + (4 * cph + 2) * H;
        const float* w3 = sW + (4 * cph + 3) * H;
        #pragma unroll
        for (int j = 0; j < H; j++) {
            float t0 = fmaf(a0, w0[j], acc[j]);
            float t1 = fmaf(a1, w1[j], t0);
            float t2 = fmaf(a2, w2[j], t1);
            acc[j]   = fmaf(a3, w3[j], t2);
        }
    }

    if (valid) {
        float4* hr = (float4*)(g_h1 + (size_t)n * H);
        #pragma unroll
        for (int cph = 0; cph < H / 4; cph++)
            hr[cph] = make_float4(acc[4*cph], acc[4*cph+1], acc[4*cph+2], acc[4*cph+3]);
    }
    stats_epilogue(acc, valid, g_s1);
}

// ---------------------------------------------------------------------------
// K3: h2 = gelu(bn1(h1)) @ W2 + b2   (streamed; BN1 inline; fused BN2 stats)
// ---------------------------------------------------------------------------
__global__ __launch_bounds__(256) void k_gemm2(const float* __restrict__ g1,
                                               const float* __restrict__ bt1,
                                               const float* __restrict__ W2,
                                               const float* __restrict__ b2,
                                               int N) {
    __shared__ float sW[H * H];
    __shared__ float sb[H], ssc[H], ssh[H];
    for (int i = threadIdx.x; i < H * H; i += blockDim.x) sW[i] = W2[i];
    if (threadIdx.x < H) sb[threadIdx.x] = b2[threadIdx.x];
    fin_inline(g_s1, g1, bt1, N, ssc, ssh);
    __syncthreads();

    int n = blockIdx.x * blockDim.x + threadIdx.x;
    bool valid = n < N;
    int nc = valid ? n : 0;
    const float4* hr = (const float4*)(g_h1 + (size_t)nc * H);

    float acc[H];
    #pragma unroll
    for (int j = 0; j < H; j++) acc[j] = sb[j];

    #pragma unroll 1
    for (int cph = 0; cph < 8; cph++) {
        float4 v = hr[cph];
        float y0 = gelu_exact(fmaf(v.x, ssc[4*cph+0], ssh[4*cph+0]));
        float y1 = gelu_exact(fmaf(v.y, ssc[4*cph+1], ssh[4*cph+1]));
        float y2 = gelu_exact(fmaf(v.z, ssc[4*cph+2], ssh[4*cph+2]));
        float y3 = gelu_exact(fmaf(v.w, ssc[4*cph+3], ssh[4*cph+3]));
        const float* w0 = sW + (4 * cph + 0) * H;
        const float* w1 = sW + (4 * cph + 1) * H;
        const float* w2 = sW + (4 * cph + 2) * H;
        const float* w3 = sW + (4 * cph + 3) * H;
        #pragma unroll
        for (int j = 0; j < H; j++) {
            float t0 = fmaf(y0, w0[j], acc[j]);
            float t1 = fmaf(y1, w1[j], t0);
            float t2 = fmaf(y2, w2[j], t1);
            acc[j]   = fmaf(y3, w3[j], t2);
        }
    }

    if (valid) {
        float4* o = (float4*)(g_h2 + (size_t)n * H);
        #pragma unroll
        for (int cph = 0; cph < H / 4; cph++)
            o[cph] = make_float4(acc[4*cph], acc[4*cph+1], acc[4*cph+2], acc[4*cph+3]);
    }
    stats_epilogue(acc, valid, g_s2);
}

// ---------------------------------------------------------------------------
// K4: out = gelu(bn2(h2)) @ W3 + b3   (gelu once into y[32]; 2 output passes)
// ---------------------------------------------------------------------------
__global__ __launch_bounds__(256) void k_out(const float* __restrict__ g2,
                                             const float* __restrict__ bt2,
                                             const float* __restrict__ W3,
                                             const float* __restrict__ b3,
                                             float* __restrict__ out,
                                             int N) {
    __shared__ float sW[H * HO];
    __shared__ float sb[HO], ssc[H], ssh[H];
    for (int i = threadIdx.x; i < H * HO; i += blockDim.x) sW[i] = W3[i];
    if (threadIdx.x < HO) sb[threadIdx.x] = b3[threadIdx.x];
    fin_inline(g_s2, g2, bt2, N, ssc, ssh);
    __syncthreads();

    int n = blockIdx.x * blockDim.x + threadIdx.x;
    if (n >= N) return;
    const float4* hr = (const float4*)(g_h2 + (size_t)n * H);
    float4* orow = (float4*)(out + (size_t)n * HO);

    float y[H];
    #pragma unroll
    for (int cph = 0; cph < 8; cph++) {
        float4 v = hr[cph];
        y[4*cph+0] = gelu_exact(fmaf(v.x, ssc[4*cph+0], ssh[4*cph+0]));
        y[4*cph+1] = gelu_exact(fmaf(v.y, ssc[4*cph+1], ssh[4*cph+1]));
        y[4*cph+2] = gelu_exact(fmaf(v.z, ssc[4*cph+2], ssh[4*cph+2]));
        y[4*cph+3] = gelu_exact(fmaf(v.w, ssc[4*cph+3], ssh[4*cph+3]));
    }

    #pragma unroll 1
    for (int jb = 0; jb < 2; jb++) {
        float acc[32];
        #pragma unroll
        for (int j = 0; j < 32; j++) acc[j] = sb[jb * 32 + j];
        #pragma unroll
        for (int k = 0; k < H; k++) {
            const float* wr = sW + k * HO + jb * 32;
            #pragma unroll
            for (int j = 0; j < 32; j++) acc[j] = fmaf(y[k], wr[j], acc[j]);
        }
        #pragma unroll
        for (int cph = 0; cph < 8; cph++)
            orow[jb * 8 + cph] = make_float4(acc[4*cph], acc[4*cph+1],
                                             acc[4*cph+2], acc[4*cph+3]);
    }
}

// ---------------------------------------------------------------------------
extern "C" void kernel_launch(void* const* d_in, const int* in_sizes, int n_in,
                              void* d_out, int out_size) {
    const float* x    = (const float*)d_in[0];
    const void*  eidx =               d_in[1];
    const float* ea   = (const float*)d_in[2];
    const float* We   = (const float*)d_in[3];
    const float* be   = (const float*)d_in[4];
    const float* W1   = (const float*)d_in[5];
    const float* b1   = (const float*)d_in[6];
    const float* g1   = (const float*)d_in[7];
    const float* bt1  = (const float*)d_in[8];
    const float* W2   = (const float*)d_in[9];
    const float* b2   = (const float*)d_in[10];
    const float* epsp = (const float*)d_in[11];
    const float* g2   = (const float*)d_in[12];
    const float* bt2  = (const float*)d_in[13];
    const float* W3   = (const float*)d_in[14];
    const float* b3   = (const float*)d_in[15];
    float* out = (float*)d_out;

    int N = in_sizes[0] / NF;
    int E = in_sizes[2] / 8;
    int n4 = N * NF / 4;
    int nb = (N + 255) / 256;

    k_pre_a<<<(n4 + 255) / 256, 256>>>(n4);
    k_pre_b<<<1, 256>>>();
    k_pre_c<<<1, 32>>>((const int*)eidx);
    k_edge <<<2048, 256>>>(x, eidx, ea, We, be, E);   // profiled (launch idx 3)
    k_gemm1<<<nb, 256>>>(x, epsp, W1, b1, N);
    k_gemm2<<<nb, 256>>>(g1, bt1, W2, b2, N);
    k_out  <<<nb, 256>>>(g2, bt2, W3, b3, out, N);
}